// round 14
// baseline (speedup 1.0000x reference)
#include <cuda_runtime.h>
#include <math.h>
#include <stdint.h>

#define BB 8
#define LL 4096
#define DD 256
#define ML (BB*LL)          // 32768 rows
#define KVS 8               // split-K for kv (deterministic)

#define AP 20    // proj/out A smem row stride ([m][k]: 16 k + 4 pad)
#define BP 136   // [k][n] smem row stride (128 + 8 pad) -> conflict-free frags

// ---- scratch (device globals; no allocations allowed) ----
__device__ float g_Q[ML*DD];       // tf32-pre-rounded
__device__ float g_K[ML*DD];       // tf32-pre-rounded
__device__ float g_V[ML*DD];       // tf32-pre-rounded
__device__ float g_Wr[3*DD*DD];    // rounded weights [w][k][n] (0=q,1=k,2=v)
__device__ float g_kvpart[KVS*BB*DD*DD];
__device__ float g_kv[BB*DD*DD];   // rounded, natural [d][h]
__device__ float g_kcs[256*DD];    // K colsum partials per 128-row block
__device__ float g_zpart[2*ML];    // z partials per 128-col block

// ---- helpers ----
__device__ __forceinline__ uint32_t f2tf(float x) {
    uint32_t r; asm("cvt.rna.tf32.f32 %0, %1;" : "=r"(r) : "f"(x)); return r;
}
__device__ __forceinline__ void mma8(float* d, const uint32_t* a, const uint32_t* b) {
    asm volatile(
        "mma.sync.aligned.m16n8k8.row.col.f32.tf32.tf32.f32 "
        "{%0,%1,%2,%3}, {%4,%5,%6,%7}, {%8,%9}, {%0,%1,%2,%3};\n"
        : "+f"(d[0]), "+f"(d[1]), "+f"(d[2]), "+f"(d[3])
        : "r"(a[0]), "r"(a[1]), "r"(a[2]), "r"(a[3]), "r"(b[0]), "r"(b[1]));
}
__device__ __forceinline__ void cp16(uint32_t saddr, const void* g) {
    asm volatile("cp.async.cg.shared.global [%0], [%1], 16;\n"
                 :: "r"(saddr), "l"(g) : "memory");
}
#define CP_COMMIT() asm volatile("cp.async.commit_group;\n" ::: "memory")
#define CP_WAIT1()  asm volatile("cp.async.wait_group 1;\n" ::: "memory")
#define CP_WAIT0()  asm volatile("cp.async.wait_group 0;\n" ::: "memory")

__device__ __forceinline__ void mma_sweep(float acc[4][4][4],
                                          const uint32_t af[4][4],
                                          const uint32_t bf[4][2]) {
    #pragma unroll
    for (int mt = 0; mt < 4; mt++)
        #pragma unroll
        for (int nt = 0; nt < 4; nt++)
            mma8(acc[mt][nt], af[mt], bf[nt]);
}

// ============================================================
// Weight pre-round: g_Wr[w][k][n] = round(W_w[k][n])
// ============================================================
__global__ void prep_w(const float* __restrict__ Wq, const float* __restrict__ Wk,
                       const float* __restrict__ Wv)
{
    const int kk = blockIdx.x, w = blockIdx.y, n = threadIdx.x;
    const float* W = (w == 0) ? Wq : (w == 1) ? Wk : Wv;
    g_Wr[(size_t)w * DD * DD + (size_t)kk * DD + n] =
        __uint_as_float(f2tf(W[(size_t)kk * DD + n]));
}

// ============================================================
// Projection: Y = act(X @ W + bias), rounded store. R11 loop.
// MODE 0: plain (V). MODE 1: +colsum (K).
// MODE 2: +z (Q) — ksum reduced in-block from g_kcs (no separate kernel).
// ============================================================
template<int ACT, int MODE>
__global__ __launch_bounds__(256)
void proj_mma(const float* __restrict__ X, const float* __restrict__ W,
              const float* __restrict__ bias, float* __restrict__ Y)
{
    __shared__ __align__(16) float As[2][128*AP];   // [m][k]
    __shared__ __align__(16) float Bs[2][16*BP];    // [k][n], pre-rounded
    __shared__ float red_s[4][128];
    __shared__ float ksum_s[128];                   // MODE 2: reduced ksum cols

    const int tid  = threadIdx.x;
    const int row0 = blockIdx.y * 128;
    const int col0 = blockIdx.x * 128;

    const int warp = tid >> 5, lane = tid & 31;
    const int wm = warp & 1, wn = warp >> 1;
    const int lr = lane >> 2, lc = lane & 3;

    const int a_r   = (2 * tid) >> 2;
    const int a_off = ((2 * tid) & 3) * 4;
    const int b_r   = (2 * tid) >> 5;
    const int b_off = ((2 * tid) & 31) * 4;

    const float* Ag = X + (size_t)(row0 + a_r) * DD + a_off;
    const float* Bg = W + (size_t)b_r * DD + col0 + b_off;

    const uint32_t sA = (uint32_t)__cvta_generic_to_shared(&As[0][0]);
    const uint32_t sB = (uint32_t)__cvta_generic_to_shared(&Bs[0][0]);

    float acc[4][4][4] = {};

    // MODE 2: reduce the 32 colsum partials for this block's 128 columns.
    // Runs before the mainloop (ksum_s is disjoint from As/Bs); value order
    // j=0..31 ascending -> bit-identical to the old reduce_kcs kernel.
    if (MODE == 2) {
        const int bbatch0 = row0 >> 12;
        if (tid < 128) {
            float s = 0.0f;
            #pragma unroll
            for (int j = 0; j < 32; j++)
                s += g_kcs[(size_t)(bbatch0 * 32 + j) * DD + col0 + tid];
            ksum_s[tid] = s;
        }
    }

    #define P_ISSUE(st, k0) do {                                               \
        cp16(sA + ((st)*128*AP + a_r*AP + a_off) * 4,     Ag + (k0));          \
        cp16(sA + ((st)*128*AP + a_r*AP + a_off + 4) * 4, Ag + (k0) + 4);      \
        cp16(sB + ((st)*16*BP + b_r*BP + b_off) * 4,      Bg + (size_t)(k0)*DD);     \
        cp16(sB + ((st)*16*BP + b_r*BP + b_off + 4) * 4,  Bg + (size_t)(k0)*DD + 4); \
    } while (0)

    #define P_LDFRAG(af, bf, st, kb) do {                                      \
        _Pragma("unroll")                                                      \
        for (int mt = 0; mt < 4; mt++) {                                       \
            const int m = wm * 64 + mt * 16 + lr;                              \
            af[mt][0] = f2tf(As[st][(m)   * AP + (kb) + lc]);                  \
            af[mt][1] = f2tf(As[st][(m+8) * AP + (kb) + lc]);                  \
            af[mt][2] = f2tf(As[st][(m)   * AP + (kb) + lc + 4]);              \
            af[mt][3] = f2tf(As[st][(m+8) * AP + (kb) + lc + 4]);              \
        }                                                                      \
        _Pragma("unroll")                                                      \
        for (int nt = 0; nt < 4; nt++) {                                       \
            const int n = wn * 32 + nt * 8 + lr;                               \
            bf[nt][0] = __float_as_uint(Bs[st][((kb) + lc)     * BP + n]);     \
            bf[nt][1] = __float_as_uint(Bs[st][((kb) + 4 + lc) * BP + n]);     \
        }                                                                      \
    } while (0)

    P_ISSUE(0, 0);  CP_COMMIT();
    P_ISSUE(1, 16); CP_COMMIT();
    CP_WAIT1();
    __syncthreads();

    uint32_t af0[4][4], bf0[4][2], af1[4][4], bf1[4][2];
    P_LDFRAG(af0, bf0, 0, 0);

    const int NST = DD / 16;   // 16
    for (int s = 0; s < NST; s++) {
        const int cur = s & 1;
        P_LDFRAG(af1, bf1, cur, 8);
        mma_sweep(acc, af0, bf0);
        __syncthreads();
        if (s + 2 < NST) { P_ISSUE(cur, (s + 2) * 16); CP_COMMIT(); }
        mma_sweep(acc, af1, bf1);
        if (s + 1 < NST) {
            if (s + 2 < NST) CP_WAIT1(); else CP_WAIT0();
            __syncthreads();
            P_LDFRAG(af0, bf0, cur ^ 1, 0);
        }
    }
    #undef P_ISSUE
    #undef P_LDFRAG

    // ---- epilogue ----
    float cs[4][2], za[4][2], ksv[4][2];
    if (MODE == 1) {
        #pragma unroll
        for (int nt = 0; nt < 4; nt++) { cs[nt][0] = 0.f; cs[nt][1] = 0.f; }
    }
    if (MODE == 2) {
        __syncthreads();   // ksum_s visible (written pre-mainloop by tid<128)
        #pragma unroll
        for (int mt = 0; mt < 4; mt++) { za[mt][0] = 0.f; za[mt][1] = 0.f; }
        #pragma unroll
        for (int nt = 0; nt < 4; nt++) {
            const int cl = wn * 32 + nt * 8 + 2 * lc;
            ksv[nt][0] = ksum_s[cl];
            ksv[nt][1] = ksum_s[cl + 1];
        }
    }

    #pragma unroll
    for (int mt = 0; mt < 4; mt++) {
        const int r0 = row0 + wm * 64 + mt * 16 + lr;
        #pragma unroll
        for (int nt = 0; nt < 4; nt++) {
            const int c = col0 + wn * 32 + nt * 8 + 2 * lc;
            const float b0 = bias[c], b1 = bias[c + 1];
            float v0 = acc[mt][nt][0] + b0;
            float v1 = acc[mt][nt][1] + b1;
            float v2 = acc[mt][nt][2] + b0;
            float v3 = acc[mt][nt][3] + b1;
            if (ACT) {
                v0 = (v0 > 0.0f) ? (v0 + 1.0f) : __expf(v0);
                v1 = (v1 > 0.0f) ? (v1 + 1.0f) : __expf(v1);
                v2 = (v2 > 0.0f) ? (v2 + 1.0f) : __expf(v2);
                v3 = (v3 > 0.0f) ? (v3 + 1.0f) : __expf(v3);
            }
            if (MODE == 1) {
                cs[nt][0] += v0 + v2;
                cs[nt][1] += v1 + v3;
            }
            if (MODE == 2) {
                za[mt][0] = fmaf(v0, ksv[nt][0], fmaf(v1, ksv[nt][1], za[mt][0]));
                za[mt][1] = fmaf(v2, ksv[nt][0], fmaf(v3, ksv[nt][1], za[mt][1]));
            }
            float2 p0 = { __uint_as_float(f2tf(v0)), __uint_as_float(f2tf(v1)) };
            float2 p1 = { __uint_as_float(f2tf(v2)), __uint_as_float(f2tf(v3)) };
            *(float2*)&Y[(size_t)r0 * DD + c]       = p0;
            *(float2*)&Y[(size_t)(r0 + 8) * DD + c] = p1;
        }
    }

    if (MODE == 1) {
        #pragma unroll
        for (int nt = 0; nt < 4; nt++) {
            #pragma unroll
            for (int off = 4; off < 32; off <<= 1) {
                cs[nt][0] += __shfl_xor_sync(0xffffffffu, cs[nt][0], off);
                cs[nt][1] += __shfl_xor_sync(0xffffffffu, cs[nt][1], off);
            }
        }
        if (lr == 0) {
            #pragma unroll
            for (int nt = 0; nt < 4; nt++) {
                const int cl = wn * 32 + nt * 8 + 2 * lc;
                red_s[wm][cl]     = cs[nt][0];
                red_s[wm][cl + 1] = cs[nt][1];
            }
        }
        __syncthreads();
        if (tid < 128)
            g_kcs[(size_t)blockIdx.y * DD + col0 + tid] = red_s[0][tid] + red_s[1][tid];
    }
    if (MODE == 2) {
        #pragma unroll
        for (int mt = 0; mt < 4; mt++) {
            #pragma unroll
            for (int off = 1; off < 4; off <<= 1) {
                za[mt][0] += __shfl_xor_sync(0xffffffffu, za[mt][0], off);
                za[mt][1] += __shfl_xor_sync(0xffffffffu, za[mt][1], off);
            }
        }
        if (lc == 0) {
            #pragma unroll
            for (int mt = 0; mt < 4; mt++) {
                const int rl = wm * 64 + mt * 16 + lr;
                red_s[wn][rl]     = za[mt][0];
                red_s[wn][rl + 8] = za[mt][1];
            }
        }
        __syncthreads();
        if (tid < 128)
            g_zpart[(size_t)blockIdx.x * ML + row0 + tid] =
                red_s[0][tid] + red_s[1][tid] + red_s[2][tid] + red_s[3][tid];
    }
}

// ============================================================
// kv split-K: kvpart[bz][d,h] = sum_{l in chunk} K[l,d]*V[l,h]
// ============================================================
__global__ __launch_bounds__(256)
void kv_mma()
{
    __shared__ __align__(16) float As[2][16*BP];   // [l][d]
    __shared__ __align__(16) float Bs[2][16*BP];   // [l][h]

    const int tid = threadIdx.x;
    const int h0 = blockIdx.x * 128;
    const int d0 = blockIdx.y * 128;
    const int bz = blockIdx.z;
    const int b  = bz / KVS;
    const int sp = bz % KVS;
    const int lchunk = LL / KVS;      // 512
    const size_t base = ((size_t)b * LL + (size_t)sp * lchunk) * DD;

    const int warp = tid >> 5, lane = tid & 31;
    const int wm = warp & 1, wn = warp >> 1;
    const int lr = lane >> 2, lc = lane & 3;

    const int k_r   = (2 * tid) >> 5;
    const int k_off = ((2 * tid) & 31) * 4;

    const float* Ag = g_K + base + (size_t)k_r * DD + d0 + k_off;
    const float* Bg = g_V + base + (size_t)k_r * DD + h0 + k_off;

    const uint32_t sA = (uint32_t)__cvta_generic_to_shared(&As[0][0]);
    const uint32_t sB = (uint32_t)__cvta_generic_to_shared(&Bs[0][0]);

    float acc[4][4][4] = {};

    #define KV_ISSUE(st, l0) do {                                              \
        cp16(sA + ((st)*16*BP + k_r*BP + k_off) * 4,     Ag + (size_t)(l0)*DD);      \
        cp16(sA + ((st)*16*BP + k_r*BP + k_off + 4) * 4, Ag + (size_t)(l0)*DD + 4);  \
        cp16(sB + ((st)*16*BP + k_r*BP + k_off) * 4,     Bg + (size_t)(l0)*DD);      \
        cp16(sB + ((st)*16*BP + k_r*BP + k_off + 4) * 4, Bg + (size_t)(l0)*DD + 4);  \
    } while (0)

    #define KV_LDFRAG(af, bf, st, kb) do {                                     \
        _Pragma("unroll")                                                      \
        for (int mt = 0; mt < 4; mt++) {                                       \
            const int m = wm * 64 + mt * 16 + lr;                              \
            af[mt][0] = __float_as_uint(As[st][((kb) + lc)     * BP + m]);     \
            af[mt][1] = __float_as_uint(As[st][((kb) + lc)     * BP + m + 8]); \
            af[mt][2] = __float_as_uint(As[st][((kb) + 4 + lc) * BP + m]);     \
            af[mt][3] = __float_as_uint(As[st][((kb) + 4 + lc) * BP + m + 8]); \
        }                                                                      \
        _Pragma("unroll")                                                      \
        for (int nt = 0; nt < 4; nt++) {                                       \
            const int n = wn * 32 + nt * 8 + lr;                               \
            bf[nt][0] = __float_as_uint(Bs[st][((kb) + lc)     * BP + n]);     \
            bf[nt][1] = __float_as_uint(Bs[st][((kb) + 4 + lc) * BP + n]);     \
        }                                                                      \
    } while (0)

    KV_ISSUE(0, 0);  CP_COMMIT();
    KV_ISSUE(1, 16); CP_COMMIT();
    CP_WAIT1();
    __syncthreads();

    uint32_t af0[4][4], bf0[4][2], af1[4][4], bf1[4][2];
    KV_LDFRAG(af0, bf0, 0, 0);

    const int NST = lchunk / 16;   // 32
    for (int s = 0; s < NST; s++) {
        const int cur = s & 1;
        KV_LDFRAG(af1, bf1, cur, 8);
        mma_sweep(acc, af0, bf0);
        __syncthreads();
        if (s + 2 < NST) { KV_ISSUE(cur, (s + 2) * 16); CP_COMMIT(); }
        mma_sweep(acc, af1, bf1);
        if (s + 1 < NST) {
            if (s + 2 < NST) CP_WAIT1(); else CP_WAIT0();
            __syncthreads();
            KV_LDFRAG(af0, bf0, cur ^ 1, 0);
        }
    }
    #undef KV_ISSUE
    #undef KV_LDFRAG

    float* outp = g_kvpart + (size_t)bz * DD * DD;
    #pragma unroll
    for (int mt = 0; mt < 4; mt++) {
        const int d = d0 + wm * 64 + mt * 16 + lr;
        #pragma unroll
        for (int nt = 0; nt < 4; nt++) {
            const int h = h0 + wn * 32 + nt * 8 + 2 * lc;
            float2 p0 = { acc[mt][nt][0], acc[mt][nt][1] };
            float2 p1 = { acc[mt][nt][2], acc[mt][nt][3] };
            *(float2*)&outp[(size_t)d * DD + h]       = p0;
            *(float2*)&outp[(size_t)(d + 8) * DD + h] = p1;
        }
    }
}

// deterministic reduce + round (natural [d][h])
__global__ void reduce_kv_kernel()
{
    int i = blockIdx.x * blockDim.x + threadIdx.x;
    if (i >= BB * DD * DD) return;
    int b  = i >> 16;
    int dh = i & 65535;
    float s = 0.0f;
    #pragma unroll
    for (int sp = 0; sp < KVS; sp++)
        s += g_kvpart[(size_t)(b * KVS + sp) * DD * DD + dh];
    g_kv[i] = __uint_as_float(f2tf(s));
}

// ============================================================
// out[row,:] = (Q[row,:] @ kv[b]) / z[row]; pre-rounded inputs.
// ============================================================
__global__ __launch_bounds__(256)
void out_mma(float* __restrict__ out)
{
    __shared__ __align__(16) float As[2][128*AP];
    __shared__ __align__(16) float Bs[2][16*BP];

    const int tid  = threadIdx.x;
    const int row0 = blockIdx.y * 128;
    const int col0 = blockIdx.x * 128;
    const int b    = row0 / LL;

    const int warp = tid >> 5, lane = tid & 31;
    const int wm = warp & 1, wn = warp >> 1;
    const int lr = lane >> 2, lc = lane & 3;

    const int a_r   = (2 * tid) >> 2;
    const int a_off = ((2 * tid) & 3) * 4;
    const int b_r   = (2 * tid) >> 5;
    const int b_off = ((2 * tid) & 31) * 4;

    const float* Ag = g_Q + (size_t)(row0 + a_r) * DD + a_off;
    const float* Bg = g_kv + (size_t)b * DD * DD + (size_t)b_r * DD + col0 + b_off;

    const uint32_t sA = (uint32_t)__cvta_generic_to_shared(&As[0][0]);
    const uint32_t sB = (uint32_t)__cvta_generic_to_shared(&Bs[0][0]);

    float acc[4][4][4] = {};

    #define O_ISSUE(st, k0) do {                                               \
        cp16(sA + ((st)*128*AP + a_r*AP + a_off) * 4,     Ag + (k0));          \
        cp16(sA + ((st)*128*AP + a_r*AP + a_off + 4) * 4, Ag + (k0) + 4);      \
        cp16(sB + ((st)*16*BP + b_r*BP + b_off) * 4,      Bg + (size_t)(k0)*DD);     \
        cp16(sB + ((st)*16*BP + b_r*BP + b_off + 4) * 4,  Bg + (size_t)(k0)*DD + 4); \
    } while (0)

    #define O_LDFRAG(af, bf, st, kb) do {                                      \
        _Pragma("unroll")                                                      \
        for (int mt = 0; mt < 4; mt++) {                                       \
            const int m = wm * 64 + mt * 16 + lr;                              \
            af[mt][0] = __float_as_uint(As[st][(m)   * AP + (kb) + lc]);       \
            af[mt][1] = __float_as_uint(As[st][(m+8) * AP + (kb) + lc]);       \
            af[mt][2] = __float_as_uint(As[st][(m)   * AP + (kb) + lc + 4]);   \
            af[mt][3] = __float_as_uint(As[st][(m+8) * AP + (kb) + lc + 4]);   \
        }                                                                      \
        _Pragma("unroll")                                                      \
        for (int nt = 0; nt < 4; nt++) {                                       \
            const int n = wn * 32 + nt * 8 + lr;                               \
            bf[nt][0] = __float_as_uint(Bs[st][((kb) + lc)     * BP + n]);     \
            bf[nt][1] = __float_as_uint(Bs[st][((kb) + 4 + lc) * BP + n]);     \
        }                                                                      \
    } while (0)

    O_ISSUE(0, 0);  CP_COMMIT();
    O_ISSUE(1, 16); CP_COMMIT();
    CP_WAIT1();
    __syncthreads();

    uint32_t af0[4][4], bf0[4][2], af1[4][4], bf1[4][2];
    O_LDFRAG(af0, bf0, 0, 0);

    const int NST = DD / 16;
    for (int s = 0; s < NST; s++) {
        const int cur = s & 1;
        O_LDFRAG(af1, bf1, cur, 8);
        mma_sweep(acc, af0, bf0);
        __syncthreads();
        if (s + 2 < NST) { O_ISSUE(cur, (s + 2) * 16); CP_COMMIT(); }
        mma_sweep(acc, af1, bf1);
        if (s + 1 < NST) {
            if (s + 2 < NST) CP_WAIT1(); else CP_WAIT0();
            __syncthreads();
            O_LDFRAG(af0, bf0, cur ^ 1, 0);
        }
    }
    #undef O_ISSUE
    #undef O_LDFRAG

    #pragma unroll
    for (int mt = 0; mt < 4; mt++) {
        const int r0 = row0 + wm * 64 + mt * 16 + lr;
        const float iz0 = 1.0f / (g_zpart[r0]     + g_zpart[ML + r0]     + 1e-6f);
        const float iz1 = 1.0f / (g_zpart[r0 + 8] + g_zpart[ML + r0 + 8] + 1e-6f);
        #pragma unroll
        for (int nt = 0; nt < 4; nt++) {
            const int c = col0 + wn * 32 + nt * 8 + 2 * lc;
            float2 p0 = { acc[mt][nt][0] * iz0, acc[mt][nt][1] * iz0 };
            float2 p1 = { acc[mt][nt][2] * iz1, acc[mt][nt][3] * iz1 };
            *(float2*)&out[(size_t)r0 * DD + c]       = p0;
            *(float2*)&out[(size_t)(r0 + 8) * DD + c] = p1;
        }
    }
}

// ============================================================
extern "C" void kernel_launch(void* const* d_in, const int* in_sizes, int n_in,
                              void* d_out, int out_size)
{
    const float* q  = (const float*)d_in[0];
    const float* k  = (const float*)d_in[1];
    const float* v  = (const float*)d_in[2];
    const float* Wq = (const float*)d_in[3];
    const float* bq = (const float*)d_in[4];
    const float* Wk = (const float*)d_in[5];
    const float* bk = (const float*)d_in[6];
    const float* Wv = (const float*)d_in[7];
    const float* bv = (const float*)d_in[8];
    float* out = (float*)d_out;

    float *dQ, *dK, *dV, *dWr;
    cudaGetSymbolAddress((void**)&dQ, g_Q);
    cudaGetSymbolAddress((void**)&dK, g_K);
    cudaGetSymbolAddress((void**)&dV, g_V);
    cudaGetSymbolAddress((void**)&dWr, g_Wr);

    // host-side resources created once (streams/events; no device memory).
    // s1/s2 are LOW priority: V-proj and kv+reduce yield SM dispatch to the
    // critical chain (K -> Q -> out) on the main stream.
    static cudaStream_t s1 = nullptr, s2 = nullptr;
    static cudaEvent_t eprep = nullptr, eK = nullptr, eV = nullptr, eKV = nullptr;
    if (s1 == nullptr) {
        int loP, hiP;
        cudaDeviceGetStreamPriorityRange(&loP, &hiP);   // loP = least priority
        cudaStreamCreateWithPriority(&s1, cudaStreamNonBlocking, loP);
        cudaStreamCreateWithPriority(&s2, cudaStreamNonBlocking, loP);
        cudaEventCreateWithFlags(&eprep, cudaEventDisableTiming);
        cudaEventCreateWithFlags(&eK,    cudaEventDisableTiming);
        cudaEventCreateWithFlags(&eV,    cudaEventDisableTiming);
        cudaEventCreateWithFlags(&eKV,   cudaEventDisableTiming);
    }

    dim3 gProj(DD / 128, ML / 128);
    dim3 gKV(DD / 128, DD / 128, BB * KVS);
    dim3 gOut(DD / 128, ML / 128);

    // 0. round weights (main)
    prep_w<<<dim3(256, 3), 256>>>(Wq, Wk, Wv);
    cudaEventRecord(eprep, 0);

    // V-proj on low-priority s1 (off the critical path)
    cudaStreamWaitEvent(s1, eprep, 0);
    proj_mma<0,0><<<gProj, 256, 0, s1>>>(v, dWr + 2 * DD * DD, bv, dV);
    cudaEventRecord(eV, s1);

    // critical chain on main: K-proj -> Q-proj (ksum fused into Q prologue)
    proj_mma<1,1><<<gProj, 256>>>(k, dWr + 1 * DD * DD, bk, dK);
    cudaEventRecord(eK, 0);
    proj_mma<1,2><<<gProj, 256>>>(q, dWr, bq, dQ);

    // kv + deterministic reduce on low-priority s2 (overlaps Q's tail)
    cudaStreamWaitEvent(s2, eK, 0);
    cudaStreamWaitEvent(s2, eV, 0);
    kv_mma<<<gKV, 256, 0, s2>>>();
    reduce_kv_kernel<<<(BB * DD * DD + 255) / 256, 256, 0, s2>>>();
    cudaEventRecord(eKV, s2);

    // tail on main: join, then out
    cudaStreamWaitEvent(0, eKV, 0);
    out_mma<<<gOut, 256>>>(out);
}

// round 15
// speedup vs baseline: 1.1469x; 1.1469x over previous
#include <cuda_runtime.h>
#include <math.h>
#include <stdint.h>

#define BB 8
#define LL 4096
#define DD 256
#define ML (BB*LL)          // 32768 rows
#define KVS 8               // split-K for kv (deterministic)

#define AP 20    // proj/out A smem row stride ([m][k]: 16 k + 4 pad)
#define BP 136   // [k][n] smem row stride (128 + 8 pad) -> conflict-free frags

// ---- scratch (device globals; no allocations allowed) ----
__device__ float g_Q[ML*DD];       // tf32-pre-rounded
__device__ float g_K[ML*DD];       // tf32-pre-rounded
__device__ float g_V[ML*DD];       // tf32-pre-rounded
__device__ float g_Wr[3*DD*DD];    // rounded weights [w][k][n] (0=q,1=k,2=v)
__device__ float g_kvpart[KVS*BB*DD*DD];
__device__ float g_kv[BB*DD*DD];   // rounded, natural [d][h]
__device__ float g_kcs[256*DD];    // K colsum partials per 128-row block
__device__ float g_ksum[BB*DD];
__device__ float g_zpart[2*ML];    // z partials per 128-col block

// ---- helpers ----
__device__ __forceinline__ uint32_t f2tf(float x) {
    uint32_t r; asm("cvt.rna.tf32.f32 %0, %1;" : "=r"(r) : "f"(x)); return r;
}
__device__ __forceinline__ void mma8(float* d, const uint32_t* a, const uint32_t* b) {
    asm volatile(
        "mma.sync.aligned.m16n8k8.row.col.f32.tf32.tf32.f32 "
        "{%0,%1,%2,%3}, {%4,%5,%6,%7}, {%8,%9}, {%0,%1,%2,%3};\n"
        : "+f"(d[0]), "+f"(d[1]), "+f"(d[2]), "+f"(d[3])
        : "r"(a[0]), "r"(a[1]), "r"(a[2]), "r"(a[3]), "r"(b[0]), "r"(b[1]));
}
__device__ __forceinline__ void cp16(uint32_t saddr, const void* g) {
    asm volatile("cp.async.cg.shared.global [%0], [%1], 16;\n"
                 :: "r"(saddr), "l"(g) : "memory");
}
#define CP_COMMIT() asm volatile("cp.async.commit_group;\n" ::: "memory")
#define CP_WAIT1()  asm volatile("cp.async.wait_group 1;\n" ::: "memory")
#define CP_WAIT0()  asm volatile("cp.async.wait_group 0;\n" ::: "memory")

__device__ __forceinline__ void mma_sweep(float acc[4][4][4],
                                          const uint32_t af[4][4],
                                          const uint32_t bf[4][2]) {
    #pragma unroll
    for (int mt = 0; mt < 4; mt++)
        #pragma unroll
        for (int nt = 0; nt < 4; nt++)
            mma8(acc[mt][nt], af[mt], bf[nt]);
}

// ============================================================
// Weight pre-round: g_Wr[w][k][n] = round(W_w[k][n])
// ============================================================
__global__ void prep_w(const float* __restrict__ Wq, const float* __restrict__ Wk,
                       const float* __restrict__ Wv)
{
    const int kk = blockIdx.x, w = blockIdx.y, n = threadIdx.x;
    const float* W = (w == 0) ? Wq : (w == 1) ? Wk : Wv;
    g_Wr[(size_t)w * DD * DD + (size_t)kk * DD + n] =
        __uint_as_float(f2tf(W[(size_t)kk * DD + n]));
}

// ============================================================
// Projection: Y = act(X @ W + bias), rounded store. R11 loop (frozen).
// MODE 0: plain (V). MODE 1: +colsum (K). MODE 2: +z (Q).
// ============================================================
template<int ACT, int MODE>
__global__ __launch_bounds__(256)
void proj_mma(const float* __restrict__ X, const float* __restrict__ W,
              const float* __restrict__ bias, float* __restrict__ Y)
{
    __shared__ __align__(16) float As[2][128*AP];   // [m][k]
    __shared__ __align__(16) float Bs[2][16*BP];    // [k][n], pre-rounded
    __shared__ float red_s[4][128];

    const int tid  = threadIdx.x;
    const int row0 = blockIdx.y * 128;
    const int col0 = blockIdx.x * 128;

    const int warp = tid >> 5, lane = tid & 31;
    const int wm = warp & 1, wn = warp >> 1;
    const int lr = lane >> 2, lc = lane & 3;

    const int a_r   = (2 * tid) >> 2;
    const int a_off = ((2 * tid) & 3) * 4;
    const int b_r   = (2 * tid) >> 5;
    const int b_off = ((2 * tid) & 31) * 4;

    const float* Ag = X + (size_t)(row0 + a_r) * DD + a_off;
    const float* Bg = W + (size_t)b_r * DD + col0 + b_off;

    const uint32_t sA = (uint32_t)__cvta_generic_to_shared(&As[0][0]);
    const uint32_t sB = (uint32_t)__cvta_generic_to_shared(&Bs[0][0]);

    float acc[4][4][4] = {};

    #define P_ISSUE(st, k0) do {                                               \
        cp16(sA + ((st)*128*AP + a_r*AP + a_off) * 4,     Ag + (k0));          \
        cp16(sA + ((st)*128*AP + a_r*AP + a_off + 4) * 4, Ag + (k0) + 4);      \
        cp16(sB + ((st)*16*BP + b_r*BP + b_off) * 4,      Bg + (size_t)(k0)*DD);     \
        cp16(sB + ((st)*16*BP + b_r*BP + b_off + 4) * 4,  Bg + (size_t)(k0)*DD + 4); \
    } while (0)

    #define P_LDFRAG(af, bf, st, kb) do {                                      \
        _Pragma("unroll")                                                      \
        for (int mt = 0; mt < 4; mt++) {                                       \
            const int m = wm * 64 + mt * 16 + lr;                              \
            af[mt][0] = f2tf(As[st][(m)   * AP + (kb) + lc]);                  \
            af[mt][1] = f2tf(As[st][(m+8) * AP + (kb) + lc]);                  \
            af[mt][2] = f2tf(As[st][(m)   * AP + (kb) + lc + 4]);              \
            af[mt][3] = f2tf(As[st][(m+8) * AP + (kb) + lc + 4]);              \
        }                                                                      \
        _Pragma("unroll")                                                      \
        for (int nt = 0; nt < 4; nt++) {                                       \
            const int n = wn * 32 + nt * 8 + lr;                               \
            bf[nt][0] = __float_as_uint(Bs[st][((kb) + lc)     * BP + n]);     \
            bf[nt][1] = __float_as_uint(Bs[st][((kb) + 4 + lc) * BP + n]);     \
        }                                                                      \
    } while (0)

    P_ISSUE(0, 0);  CP_COMMIT();
    P_ISSUE(1, 16); CP_COMMIT();
    CP_WAIT1();
    __syncthreads();

    uint32_t af0[4][4], bf0[4][2], af1[4][4], bf1[4][2];
    P_LDFRAG(af0, bf0, 0, 0);

    const int NST = DD / 16;   // 16
    for (int s = 0; s < NST; s++) {
        const int cur = s & 1;
        P_LDFRAG(af1, bf1, cur, 8);
        mma_sweep(acc, af0, bf0);
        __syncthreads();
        if (s + 2 < NST) { P_ISSUE(cur, (s + 2) * 16); CP_COMMIT(); }
        mma_sweep(acc, af1, bf1);
        if (s + 1 < NST) {
            if (s + 2 < NST) CP_WAIT1(); else CP_WAIT0();
            __syncthreads();
            P_LDFRAG(af0, bf0, cur ^ 1, 0);
        }
    }
    #undef P_ISSUE
    #undef P_LDFRAG

    // ---- epilogue ----
    const int bbatch = row0 >> 12;
    float cs[4][2], za[4][2], ksv[4][2];
    if (MODE == 1) {
        #pragma unroll
        for (int nt = 0; nt < 4; nt++) { cs[nt][0] = 0.f; cs[nt][1] = 0.f; }
    }
    if (MODE == 2) {
        #pragma unroll
        for (int mt = 0; mt < 4; mt++) { za[mt][0] = 0.f; za[mt][1] = 0.f; }
        #pragma unroll
        for (int nt = 0; nt < 4; nt++) {
            const int c = col0 + wn * 32 + nt * 8 + 2 * lc;
            ksv[nt][0] = g_ksum[bbatch * DD + c];
            ksv[nt][1] = g_ksum[bbatch * DD + c + 1];
        }
    }

    #pragma unroll
    for (int mt = 0; mt < 4; mt++) {
        const int r0 = row0 + wm * 64 + mt * 16 + lr;
        #pragma unroll
        for (int nt = 0; nt < 4; nt++) {
            const int c = col0 + wn * 32 + nt * 8 + 2 * lc;
            const float b0 = bias[c], b1 = bias[c + 1];
            float v0 = acc[mt][nt][0] + b0;
            float v1 = acc[mt][nt][1] + b1;
            float v2 = acc[mt][nt][2] + b0;
            float v3 = acc[mt][nt][3] + b1;
            if (ACT) {
                v0 = (v0 > 0.0f) ? (v0 + 1.0f) : __expf(v0);
                v1 = (v1 > 0.0f) ? (v1 + 1.0f) : __expf(v1);
                v2 = (v2 > 0.0f) ? (v2 + 1.0f) : __expf(v2);
                v3 = (v3 > 0.0f) ? (v3 + 1.0f) : __expf(v3);
            }
            if (MODE == 1) {
                cs[nt][0] += v0 + v2;
                cs[nt][1] += v1 + v3;
            }
            if (MODE == 2) {
                za[mt][0] = fmaf(v0, ksv[nt][0], fmaf(v1, ksv[nt][1], za[mt][0]));
                za[mt][1] = fmaf(v2, ksv[nt][0], fmaf(v3, ksv[nt][1], za[mt][1]));
            }
            float2 p0 = { __uint_as_float(f2tf(v0)), __uint_as_float(f2tf(v1)) };
            float2 p1 = { __uint_as_float(f2tf(v2)), __uint_as_float(f2tf(v3)) };
            *(float2*)&Y[(size_t)r0 * DD + c]       = p0;
            *(float2*)&Y[(size_t)(r0 + 8) * DD + c] = p1;
        }
    }

    if (MODE == 1) {
        #pragma unroll
        for (int nt = 0; nt < 4; nt++) {
            #pragma unroll
            for (int off = 4; off < 32; off <<= 1) {
                cs[nt][0] += __shfl_xor_sync(0xffffffffu, cs[nt][0], off);
                cs[nt][1] += __shfl_xor_sync(0xffffffffu, cs[nt][1], off);
            }
        }
        if (lr == 0) {
            #pragma unroll
            for (int nt = 0; nt < 4; nt++) {
                const int cl = wn * 32 + nt * 8 + 2 * lc;
                red_s[wm][cl]     = cs[nt][0];
                red_s[wm][cl + 1] = cs[nt][1];
            }
        }
        __syncthreads();
        if (tid < 128)
            g_kcs[(size_t)blockIdx.y * DD + col0 + tid] = red_s[0][tid] + red_s[1][tid];
    }
    if (MODE == 2) {
        #pragma unroll
        for (int mt = 0; mt < 4; mt++) {
            #pragma unroll
            for (int off = 1; off < 4; off <<= 1) {
                za[mt][0] += __shfl_xor_sync(0xffffffffu, za[mt][0], off);
                za[mt][1] += __shfl_xor_sync(0xffffffffu, za[mt][1], off);
            }
        }
        if (lc == 0) {
            #pragma unroll
            for (int mt = 0; mt < 4; mt++) {
                const int rl = wm * 64 + mt * 16 + lr;
                red_s[wn][rl]     = za[mt][0];
                red_s[wn][rl + 8] = za[mt][1];
            }
        }
        __syncthreads();
        if (tid < 128)
            g_zpart[(size_t)blockIdx.x * ML + row0 + tid] =
                red_s[0][tid] + red_s[1][tid] + red_s[2][tid] + red_s[3][tid];
    }
}

// ksum[b,d] = sum over 32 row-blocks of g_kcs
__global__ void reduce_kcs_kernel()
{
    int i = blockIdx.x * blockDim.x + threadIdx.x;
    if (i >= BB * DD) return;
    int b = i / DD, d = i % DD;
    float s = 0.0f;
    #pragma unroll
    for (int j = 0; j < 32; j++)
        s += g_kcs[(size_t)(b * 32 + j) * DD + d];
    g_ksum[i] = s;
}

// ============================================================
// kv split-K: kvpart[bz][d,h] = sum_{l in chunk} K[l,d]*V[l,h]
// ============================================================
__global__ __launch_bounds__(256)
void kv_mma()
{
    __shared__ __align__(16) float As[2][16*BP];   // [l][d]
    __shared__ __align__(16) float Bs[2][16*BP];   // [l][h]

    const int tid = threadIdx.x;
    const int h0 = blockIdx.x * 128;
    const int d0 = blockIdx.y * 128;
    const int bz = blockIdx.z;
    const int b  = bz / KVS;
    const int sp = bz % KVS;
    const int lchunk = LL / KVS;      // 512
    const size_t base = ((size_t)b * LL + (size_t)sp * lchunk) * DD;

    const int warp = tid >> 5, lane = tid & 31;
    const int wm = warp & 1, wn = warp >> 1;
    const int lr = lane >> 2, lc = lane & 3;

    const int k_r   = (2 * tid) >> 5;
    const int k_off = ((2 * tid) & 31) * 4;

    const float* Ag = g_K + base + (size_t)k_r * DD + d0 + k_off;
    const float* Bg = g_V + base + (size_t)k_r * DD + h0 + k_off;

    const uint32_t sA = (uint32_t)__cvta_generic_to_shared(&As[0][0]);
    const uint32_t sB = (uint32_t)__cvta_generic_to_shared(&Bs[0][0]);

    float acc[4][4][4] = {};

    #define KV_ISSUE(st, l0) do {                                              \
        cp16(sA + ((st)*16*BP + k_r*BP + k_off) * 4,     Ag + (size_t)(l0)*DD);      \
        cp16(sA + ((st)*16*BP + k_r*BP + k_off + 4) * 4, Ag + (size_t)(l0)*DD + 4);  \
        cp16(sB + ((st)*16*BP + k_r*BP + k_off) * 4,     Bg + (size_t)(l0)*DD);      \
        cp16(sB + ((st)*16*BP + k_r*BP + k_off + 4) * 4, Bg + (size_t)(l0)*DD + 4);  \
    } while (0)

    #define KV_LDFRAG(af, bf, st, kb) do {                                     \
        _Pragma("unroll")                                                      \
        for (int mt = 0; mt < 4; mt++) {                                       \
            const int m = wm * 64 + mt * 16 + lr;                              \
            af[mt][0] = __float_as_uint(As[st][((kb) + lc)     * BP + m]);     \
            af[mt][1] = __float_as_uint(As[st][((kb) + lc)     * BP + m + 8]); \
            af[mt][2] = __float_as_uint(As[st][((kb) + 4 + lc) * BP + m]);     \
            af[mt][3] = __float_as_uint(As[st][((kb) + 4 + lc) * BP + m + 8]); \
        }                                                                      \
        _Pragma("unroll")                                                      \
        for (int nt = 0; nt < 4; nt++) {                                       \
            const int n = wn * 32 + nt * 8 + lr;                               \
            bf[nt][0] = __float_as_uint(Bs[st][((kb) + lc)     * BP + n]);     \
            bf[nt][1] = __float_as_uint(Bs[st][((kb) + 4 + lc) * BP + n]);     \
        }                                                                      \
    } while (0)

    KV_ISSUE(0, 0);  CP_COMMIT();
    KV_ISSUE(1, 16); CP_COMMIT();
    CP_WAIT1();
    __syncthreads();

    uint32_t af0[4][4], bf0[4][2], af1[4][4], bf1[4][2];
    KV_LDFRAG(af0, bf0, 0, 0);

    const int NST = lchunk / 16;   // 32
    for (int s = 0; s < NST; s++) {
        const int cur = s & 1;
        KV_LDFRAG(af1, bf1, cur, 8);
        mma_sweep(acc, af0, bf0);
        __syncthreads();
        if (s + 2 < NST) { KV_ISSUE(cur, (s + 2) * 16); CP_COMMIT(); }
        mma_sweep(acc, af1, bf1);
        if (s + 1 < NST) {
            if (s + 2 < NST) CP_WAIT1(); else CP_WAIT0();
            __syncthreads();
            KV_LDFRAG(af0, bf0, cur ^ 1, 0);
        }
    }
    #undef KV_ISSUE
    #undef KV_LDFRAG

    float* outp = g_kvpart + (size_t)bz * DD * DD;
    #pragma unroll
    for (int mt = 0; mt < 4; mt++) {
        const int d = d0 + wm * 64 + mt * 16 + lr;
        #pragma unroll
        for (int nt = 0; nt < 4; nt++) {
            const int h = h0 + wn * 32 + nt * 8 + 2 * lc;
            float2 p0 = { acc[mt][nt][0], acc[mt][nt][1] };
            float2 p1 = { acc[mt][nt][2], acc[mt][nt][3] };
            *(float2*)&outp[(size_t)d * DD + h]       = p0;
            *(float2*)&outp[(size_t)(d + 8) * DD + h] = p1;
        }
    }
}

// deterministic reduce + round (natural [d][h])
__global__ void reduce_kv_kernel()
{
    int i = blockIdx.x * blockDim.x + threadIdx.x;
    if (i >= BB * DD * DD) return;
    int b  = i >> 16;
    int dh = i & 65535;
    float s = 0.0f;
    #pragma unroll
    for (int sp = 0; sp < KVS; sp++)
        s += g_kvpart[(size_t)(b * KVS + sp) * DD * DD + dh];
    g_kv[i] = __uint_as_float(f2tf(s));
}

// ============================================================
// out[row,:] = (Q[row,:] @ kv[b]) / z[row]; pre-rounded inputs.
// ============================================================
__global__ __launch_bounds__(256)
void out_mma(float* __restrict__ out)
{
    __shared__ __align__(16) float As[2][128*AP];
    __shared__ __align__(16) float Bs[2][16*BP];

    const int tid  = threadIdx.x;
    const int row0 = blockIdx.y * 128;
    const int col0 = blockIdx.x * 128;
    const int b    = row0 / LL;

    const int warp = tid >> 5, lane = tid & 31;
    const int wm = warp & 1, wn = warp >> 1;
    const int lr = lane >> 2, lc = lane & 3;

    const int a_r   = (2 * tid) >> 2;
    const int a_off = ((2 * tid) & 3) * 4;
    const int b_r   = (2 * tid) >> 5;
    const int b_off = ((2 * tid) & 31) * 4;

    const float* Ag = g_Q + (size_t)(row0 + a_r) * DD + a_off;
    const float* Bg = g_kv + (size_t)b * DD * DD + (size_t)b_r * DD + col0 + b_off;

    const uint32_t sA = (uint32_t)__cvta_generic_to_shared(&As[0][0]);
    const uint32_t sB = (uint32_t)__cvta_generic_to_shared(&Bs[0][0]);

    float acc[4][4][4] = {};

    #define O_ISSUE(st, k0) do {                                               \
        cp16(sA + ((st)*128*AP + a_r*AP + a_off) * 4,     Ag + (k0));          \
        cp16(sA + ((st)*128*AP + a_r*AP + a_off + 4) * 4, Ag + (k0) + 4);      \
        cp16(sB + ((st)*16*BP + b_r*BP + b_off) * 4,      Bg + (size_t)(k0)*DD);     \
        cp16(sB + ((st)*16*BP + b_r*BP + b_off + 4) * 4,  Bg + (size_t)(k0)*DD + 4); \
    } while (0)

    #define O_LDFRAG(af, bf, st, kb) do {                                      \
        _Pragma("unroll")                                                      \
        for (int mt = 0; mt < 4; mt++) {                                       \
            const int m = wm * 64 + mt * 16 + lr;                              \
            af[mt][0] = __float_as_uint(As[st][(m)   * AP + (kb) + lc]);       \
            af[mt][1] = __float_as_uint(As[st][(m+8) * AP + (kb) + lc]);       \
            af[mt][2] = __float_as_uint(As[st][(m)   * AP + (kb) + lc + 4]);   \
            af[mt][3] = __float_as_uint(As[st][(m+8) * AP + (kb) + lc + 4]);   \
        }                                                                      \
        _Pragma("unroll")                                                      \
        for (int nt = 0; nt < 4; nt++) {                                       \
            const int n = wn * 32 + nt * 8 + lr;                               \
            bf[nt][0] = __float_as_uint(Bs[st][((kb) + lc)     * BP + n]);     \
            bf[nt][1] = __float_as_uint(Bs[st][((kb) + 4 + lc) * BP + n]);     \
        }                                                                      \
    } while (0)

    O_ISSUE(0, 0);  CP_COMMIT();
    O_ISSUE(1, 16); CP_COMMIT();
    CP_WAIT1();
    __syncthreads();

    uint32_t af0[4][4], bf0[4][2], af1[4][4], bf1[4][2];
    O_LDFRAG(af0, bf0, 0, 0);

    const int NST = DD / 16;
    for (int s = 0; s < NST; s++) {
        const int cur = s & 1;
        O_LDFRAG(af1, bf1, cur, 8);
        mma_sweep(acc, af0, bf0);
        __syncthreads();
        if (s + 2 < NST) { O_ISSUE(cur, (s + 2) * 16); CP_COMMIT(); }
        mma_sweep(acc, af1, bf1);
        if (s + 1 < NST) {
            if (s + 2 < NST) CP_WAIT1(); else CP_WAIT0();
            __syncthreads();
            O_LDFRAG(af0, bf0, cur ^ 1, 0);
        }
    }
    #undef O_ISSUE
    #undef O_LDFRAG

    #pragma unroll
    for (int mt = 0; mt < 4; mt++) {
        const int r0 = row0 + wm * 64 + mt * 16 + lr;
        const float iz0 = 1.0f / (g_zpart[r0]     + g_zpart[ML + r0]     + 1e-6f);
        const float iz1 = 1.0f / (g_zpart[r0 + 8] + g_zpart[ML + r0 + 8] + 1e-6f);
        #pragma unroll
        for (int nt = 0; nt < 4; nt++) {
            const int c = col0 + wn * 32 + nt * 8 + 2 * lc;
            float2 p0 = { acc[mt][nt][0] * iz0, acc[mt][nt][1] * iz0 };
            float2 p1 = { acc[mt][nt][2] * iz1, acc[mt][nt][3] * iz1 };
            *(float2*)&out[(size_t)r0 * DD + c]       = p0;
            *(float2*)&out[(size_t)(r0 + 8) * DD + c] = p1;
        }
    }
}

// ============================================================
extern "C" void kernel_launch(void* const* d_in, const int* in_sizes, int n_in,
                              void* d_out, int out_size)
{
    const float* q  = (const float*)d_in[0];
    const float* k  = (const float*)d_in[1];
    const float* v  = (const float*)d_in[2];
    const float* Wq = (const float*)d_in[3];
    const float* bq = (const float*)d_in[4];
    const float* Wk = (const float*)d_in[5];
    const float* bk = (const float*)d_in[6];
    const float* Wv = (const float*)d_in[7];
    const float* bv = (const float*)d_in[8];
    float* out = (float*)d_out;

    float *dQ, *dK, *dV, *dWr;
    cudaGetSymbolAddress((void**)&dQ, g_Q);
    cudaGetSymbolAddress((void**)&dK, g_K);
    cudaGetSymbolAddress((void**)&dV, g_V);
    cudaGetSymbolAddress((void**)&dWr, g_Wr);

    // host-side resources created once (streams/events; no device memory).
    // s1/s2 are LOW priority: V-proj and kv+reduce yield SM dispatch to the
    // critical chain (K -> ksum -> Q -> out) on the main stream.
    static cudaStream_t s1 = nullptr, s2 = nullptr;
    static cudaEvent_t eprep = nullptr, eK = nullptr, eV = nullptr, eKV = nullptr;
    if (s1 == nullptr) {
        int loP, hiP;
        cudaDeviceGetStreamPriorityRange(&loP, &hiP);   // loP = least priority
        cudaStreamCreateWithPriority(&s1, cudaStreamNonBlocking, loP);
        cudaStreamCreateWithPriority(&s2, cudaStreamNonBlocking, loP);
        cudaEventCreateWithFlags(&eprep, cudaEventDisableTiming);
        cudaEventCreateWithFlags(&eK,    cudaEventDisableTiming);
        cudaEventCreateWithFlags(&eV,    cudaEventDisableTiming);
        cudaEventCreateWithFlags(&eKV,   cudaEventDisableTiming);
    }

    dim3 gProj(DD / 128, ML / 128);
    dim3 gKV(DD / 128, DD / 128, BB * KVS);
    dim3 gOut(DD / 128, ML / 128);

    // 0. round weights (main)
    prep_w<<<dim3(256, 3), 256>>>(Wq, Wk, Wv);
    cudaEventRecord(eprep, 0);

    // V-proj on low-priority s1 (off the critical path)
    cudaStreamWaitEvent(s1, eprep, 0);
    proj_mma<0,0><<<gProj, 256, 0, s1>>>(v, dWr + 2 * DD * DD, bv, dV);
    cudaEventRecord(eV, s1);

    // critical chain on main: K-proj -> ksum -> Q-proj (no wait on V)
    proj_mma<1,1><<<gProj, 256>>>(k, dWr + 1 * DD * DD, bk, dK);
    cudaEventRecord(eK, 0);
    reduce_kcs_kernel<<<(BB * DD + 255) / 256, 256>>>();
    proj_mma<1,2><<<gProj, 256>>>(q, dWr, bq, dQ);

    // kv + deterministic reduce on low-priority s2 (overlaps Q's tail)
    cudaStreamWaitEvent(s2, eK, 0);
    cudaStreamWaitEvent(s2, eV, 0);
    kv_mma<<<gKV, 256, 0, s2>>>();
    reduce_kv_kernel<<<(BB * DD * DD + 255) / 256, 256, 0, s2>>>();
    cudaEventRecord(eKV, s2);

    // tail on main: join, then out
    cudaStreamWaitEvent(0, eKV, 0);
    out_mma<<<gOut, 256>>>(out);
}